// round 5
// baseline (speedup 1.0000x reference)
#include <cuda_runtime.h>
#include <math.h>

#define BB 64
#define LL 512
#define HLL 512
#define HSS 512
#define EE 256
#define KK 128
#define VV 128
#define CC 34
#define TT 200
#define TP1 201

// ---------------- device scratch (static, no runtime alloc) ----------------
__device__ float g_keypT[BB * KK * LL];   // [b][k][l]  16 MB
__device__ float g_valp [BB * LL * VV];   // [b][l][v]  16 MB
__device__ float g_h1[2][BB * HSS];
__device__ float g_c1[2][BB * HSS];
__device__ float g_h2[2][BB * HSS];
__device__ float g_c2[2][BB * HSS];
__device__ float g_ctx[2][BB * VV];

// ---------------- init: copy initial states into parity-0 buffers ----------
__global__ void init_kernel(const float* __restrict__ h1_0, const float* __restrict__ c1_0,
                            const float* __restrict__ h2_0, const float* __restrict__ c2_0) {
    int i = blockIdx.x * blockDim.x + threadIdx.x;
    if (i < BB * HSS) {
        g_h1[0][i] = h1_0[i];
        g_c1[0][i] = c1_0[i];
        g_h2[0][i] = h2_0[i];
        g_c2[0][i] = c2_0[i];
    }
}

// ---------------- precompute keypT / valp ----------------------------------
// grid: (L/32=16, ngroup=2, B=64), 256 threads.
// block computes 32 l-rows x 128 n-cols of (listener @ W^T + b)
__global__ __launch_bounds__(256) void precompute_kernel(
    const float* __restrict__ listener,
    const float* __restrict__ Wh, const float* __restrict__ bh,
    const float* __restrict__ Wv, const float* __restrict__ bv) {
    __shared__ __align__(16) float A_s[32][36];   // [k][l]
    __shared__ __align__(16) float W_s[32][132];  // [k][n]

    const int b   = blockIdx.z;
    const int ng  = blockIdx.y;        // 0 -> key, 1 -> val
    const int l0t = blockIdx.x * 32;
    const int tid = threadIdx.x;
    const float* W    = ng ? Wv : Wh;
    const float* bias = ng ? bv : bh;

    const int n0 = (tid & 31) * 4;
    const int l0 = (tid >> 5) * 4;
    float acc[4][4] = {};   // [l][n]

    for (int kc = 0; kc < HLL; kc += 32) {
        // A tile: 32l x 32k  (1024 elems / 256 thr = 4)
        #pragma unroll
        for (int it = 0; it < 4; ++it) {
            int idx = tid + it * 256;
            int k = idx & 31, l = idx >> 5;
            A_s[k][l] = listener[((size_t)b * LL + l0t + l) * HLL + kc + k];
        }
        // W tile: 128n x 32k (4096 / 256 = 16)
        #pragma unroll
        for (int it = 0; it < 16; ++it) {
            int idx = tid + it * 256;
            int k = idx & 31, n = idx >> 5;
            W_s[k][n] = W[(size_t)n * HLL + kc + k];
        }
        __syncthreads();
        #pragma unroll
        for (int k = 0; k < 32; ++k) {
            float4 a4 = *reinterpret_cast<const float4*>(&A_s[k][l0]);
            float4 w4 = *reinterpret_cast<const float4*>(&W_s[k][n0]);
            float al[4] = {a4.x, a4.y, a4.z, a4.w};
            float wn[4] = {w4.x, w4.y, w4.z, w4.w};
            #pragma unroll
            for (int i = 0; i < 4; ++i)
                #pragma unroll
                for (int j = 0; j < 4; ++j)
                    acc[i][j] += al[i] * wn[j];
        }
        __syncthreads();
    }

    float bn[4] = {bias[n0], bias[n0 + 1], bias[n0 + 2], bias[n0 + 3]};
    if (ng == 0) {
        // keypT[b][n][l]
        #pragma unroll
        for (int j = 0; j < 4; ++j)       // n
            #pragma unroll
            for (int i = 0; i < 4; ++i)   // l
                g_keypT[(size_t)b * KK * LL + (size_t)(n0 + j) * LL + (l0t + l0 + i)] =
                    acc[i][j] + bn[j];
    } else {
        // valp[b][l][v]
        #pragma unroll
        for (int i = 0; i < 4; ++i)
            #pragma unroll
            for (int j = 0; j < 4; ++j)
                g_valp[(size_t)b * LL * VV + (size_t)(l0t + l0 + i) * VV + (n0 + j)] =
                    acc[i][j] + bn[j];
    }
}

// ---------------- LSTM step (gates GEMM + fused cell update) ---------------
// grid 128 blocks x 128 threads. Block bn handles units u in [4*bn, 4*bn+4),
// all 4 gates (16 j rows), all 64 batch. jj = gate*4 + u_local.
template <int LAYER>
__global__ __launch_bounds__(128) void lstm_kernel(
    const float* __restrict__ embed, const int* __restrict__ targets,
    const float* __restrict__ Wih, const float* __restrict__ bih,
    const float* __restrict__ Whh, const float* __restrict__ bhh,
    int p, int t) {
    __shared__ __align__(16) float A_s[32][68];  // [k][b]
    __shared__ float W_s[32][20];                // [k][jj]
    __shared__ float G_s[16][65];                // [jj][b]
    __shared__ int   tgt_s[64];

    const int tid    = threadIdx.x;
    const int u_base = blockIdx.x * 4;

    const float *xsrc, *hsrc, *csrc;
    float *hdst, *cdst;
    if (LAYER == 1) {
        xsrc = g_ctx[p];     hsrc = g_h1[p]; csrc = g_c1[p];
        hdst = g_h1[1 - p];  cdst = g_c1[1 - p];
    } else {
        xsrc = g_h1[1 - p];  hsrc = g_h2[p]; csrc = g_c2[p];
        hdst = g_h2[1 - p];  cdst = g_c2[1 - p];
    }
    if (LAYER == 1 && tid < 64) tgt_s[tid] = targets[tid * TP1 + t];
    __syncthreads();

    const int KTOT = (LAYER == 1) ? 896 : 1024;
    const int j0 = (tid >> 4) * 2;     // 0..14
    const int b0 = (tid & 15) * 4;     // 0..60
    float acc[2][4] = {};

    for (int kc = 0; kc < KTOT; kc += 32) {
        // A tile: 64b x 32k  (2048 / 128 = 16)
        #pragma unroll
        for (int it = 0; it < 16; ++it) {
            int idx = tid + it * 128;
            int k = idx & 31, b = idx >> 5;
            int kg = kc + k;
            float v;
            if (LAYER == 1) {
                if (kg < 256)      v = embed[tgt_s[b] * EE + kg];
                else if (kg < 384) v = xsrc[b * VV + kg - 256];
                else               v = hsrc[b * HSS + kg - 384];
            } else {
                if (kg < 512)      v = xsrc[b * HSS + kg];
                else               v = hsrc[b * HSS + kg - 512];
            }
            A_s[k][b] = v;
        }
        // W tile: 16jj x 32k  (512 / 128 = 4)
        #pragma unroll
        for (int it = 0; it < 4; ++it) {
            int idx = tid + it * 128;
            int k = idx & 31, jj = idx >> 5;
            int gate = jj >> 2, ul = jj & 3;
            int r = gate * HSS + u_base + ul;
            int kg = kc + k;
            float wv;
            if (LAYER == 1)
                wv = (kg < 384) ? Wih[(size_t)r * 384 + kg]
                                : Whh[(size_t)r * HSS + kg - 384];
            else
                wv = (kg < 512) ? Wih[(size_t)r * HSS + kg]
                                : Whh[(size_t)r * HSS + kg - 512];
            W_s[k][jj] = wv;
        }
        __syncthreads();
        #pragma unroll
        for (int k = 0; k < 32; ++k) {
            float4 a = *reinterpret_cast<const float4*>(&A_s[k][b0]);
            float w0 = W_s[k][j0], w1 = W_s[k][j0 + 1];
            acc[0][0] += w0 * a.x; acc[0][1] += w0 * a.y;
            acc[0][2] += w0 * a.z; acc[0][3] += w0 * a.w;
            acc[1][0] += w1 * a.x; acc[1][1] += w1 * a.y;
            acc[1][2] += w1 * a.z; acc[1][3] += w1 * a.w;
        }
        __syncthreads();
    }

    // stash gates (+bias) to smem
    #pragma unroll
    for (int jd = 0; jd < 2; ++jd) {
        int jj = j0 + jd;
        int gate = jj >> 2, ul = jj & 3;
        int r = gate * HSS + u_base + ul;
        float bsum = bih[r] + bhh[r];
        #pragma unroll
        for (int bi = 0; bi < 4; ++bi)
            G_s[jj][b0 + bi] = acc[jd][bi] + bsum;
    }
    __syncthreads();

    // fused cell update: 4u x 64b = 256 pairs, 2 per thread
    #pragma unroll
    for (int pr = 0; pr < 2; ++pr) {
        int pair = tid + pr * 128;
        int ul = pair >> 6, b = pair & 63;
        float gi = G_s[0 + ul][b];
        float gf = G_s[4 + ul][b];
        float gg = G_s[8 + ul][b];
        float go = G_s[12 + ul][b];
        int u = u_base + ul;
        float cp = csrc[b * HSS + u];
        float si = 1.f / (1.f + expf(-gi));
        float sf = 1.f / (1.f + expf(-gf));
        float so = 1.f / (1.f + expf(-go));
        float cn = sf * cp + si * tanhf(gg);
        cdst[b * HSS + u] = cn;
        hdst[b * HSS + u] = so * tanhf(cn);
    }
}

// ---------------- attention + logits (one block per batch) -----------------
__global__ __launch_bounds__(256) void attend_kernel(
    int h2_idx, int ctx_idx,
    const float* __restrict__ Ws, const float* __restrict__ bs,
    const float* __restrict__ Wout, const float* __restrict__ bout,
    const int* __restrict__ outputs_length,
    float* __restrict__ out, int t) {
    __shared__ float h2s[512];
    __shared__ float q_s[128];
    __shared__ float attn_s[512];
    __shared__ float ctx_s[128];
    __shared__ float red[256];

    const int b = blockIdx.x;
    const int tid = threadIdx.x;
    const int lane = tid & 31, wrp = tid >> 5;

    h2s[tid]       = g_h2[h2_idx][b * HSS + tid];
    h2s[tid + 256] = g_h2[h2_idx][b * HSS + tid + 256];
    __syncthreads();

    // q = h2 @ Ws^T + bs   (warp per row)
    for (int k = wrp; k < KK; k += 8) {
        const float* wr = Ws + (size_t)k * HSS;
        float s = 0.f;
        #pragma unroll
        for (int j = lane; j < 512; j += 32) s += wr[j] * h2s[j];
        #pragma unroll
        for (int o = 16; o > 0; o >>= 1) s += __shfl_xor_sync(0xffffffffu, s, o);
        if (lane == 0) q_s[k] = s + bs[k];
    }
    __syncthreads();

    const int len = (b == 0) ? LL : outputs_length[b];  // mask.at[0].set(1.0)
    const int l1 = tid, l2 = tid + 256;
    float e1 = 0.f, e2 = 0.f;
    const float* kp = g_keypT + (size_t)b * KK * LL;
    #pragma unroll 4
    for (int k = 0; k < KK; ++k) {
        float qk = q_s[k];
        e1 += qk * kp[k * LL + l1];
        e2 += qk * kp[k * LL + l2];
    }
    float m1 = (l1 < len) ? e1 : -1e30f;
    float m2 = (l2 < len) ? e2 : -1e30f;
    red[tid] = fmaxf(m1, m2);
    __syncthreads();
    for (int s = 128; s > 0; s >>= 1) {
        if (tid < s) red[tid] = fmaxf(red[tid], red[tid + s]);
        __syncthreads();
    }
    float mx = red[0];
    __syncthreads();
    float p1 = (l1 < len) ? expf(e1 - mx) : 0.f;
    float p2 = (l2 < len) ? expf(e2 - mx) : 0.f;
    red[tid] = p1 + p2;
    __syncthreads();
    for (int s = 128; s > 0; s >>= 1) {
        if (tid < s) red[tid] += red[tid + s];
        __syncthreads();
    }
    float inv = 1.f / fmaxf(red[0], 1e-12f);
    float a1 = p1 * inv, a2 = p2 * inv;
    attn_s[l1] = a1;
    attn_s[l2] = a2;
    if (t >= 0) {
        float* ao = out + (size_t)BB * TT * CC + ((size_t)b * TT + t) * LL;
        ao[l1] = a1;
        ao[l2] = a2;
    }
    __syncthreads();

    // ctx = attn @ valp
    {
        int v = tid & 127, half = tid >> 7;
        const float* vp = g_valp + (size_t)b * LL * VV;
        float s = 0.f;
        int lbeg = half * 256;
        #pragma unroll 4
        for (int l = lbeg; l < lbeg + 256; ++l) s += attn_s[l] * vp[l * VV + v];
        red[tid] = s;
    }
    __syncthreads();
    if (tid < 128) {
        float c = red[tid] + red[tid + 128];
        ctx_s[tid] = c;
        g_ctx[ctx_idx][b * VV + tid] = c;
    }
    __syncthreads();

    // logits = [h2 | ctx] @ Wout^T + bout
    if (t >= 0) {
        for (int c = wrp; c < CC; c += 8) {
            const float* wr = Wout + (size_t)c * (HSS + VV);
            float s = 0.f;
            #pragma unroll
            for (int j = lane; j < 512; j += 32) s += wr[j] * h2s[j];
            #pragma unroll
            for (int j = lane; j < 128; j += 32) s += wr[512 + j] * ctx_s[j];
            #pragma unroll
            for (int o = 16; o > 0; o >>= 1) s += __shfl_xor_sync(0xffffffffu, s, o);
            if (lane == 0) out[((size_t)b * TT + t) * CC + c] = s + bout[c];
        }
    }
}

// ---------------- launch ----------------------------------------------------
extern "C" void kernel_launch(void* const* d_in, const int* in_sizes, int n_in,
                              void* d_out, int out_size) {
    const float* listener       = (const float*)d_in[0];
    const int*   outputs_length = (const int*)  d_in[1];
    const int*   targets        = (const int*)  d_in[2];
    // d_in[3] = teacher_forcing (unused by the math)
    const float* embed = (const float*)d_in[4];
    const float* Ws    = (const float*)d_in[5];
    const float* bs    = (const float*)d_in[6];
    const float* Wh    = (const float*)d_in[7];
    const float* bh    = (const float*)d_in[8];
    const float* Wv    = (const float*)d_in[9];
    const float* bv    = (const float*)d_in[10];
    const float* Wih1  = (const float*)d_in[11];
    const float* bih1  = (const float*)d_in[12];
    const float* Whh1  = (const float*)d_in[13];
    const float* bhh1  = (const float*)d_in[14];
    const float* Wih2  = (const float*)d_in[15];
    const float* bih2  = (const float*)d_in[16];
    const float* Whh2  = (const float*)d_in[17];
    const float* bhh2  = (const float*)d_in[18];
    const float* Wout  = (const float*)d_in[19];
    const float* bout  = (const float*)d_in[20];
    const float* h1_0  = (const float*)d_in[21];
    const float* c1_0  = (const float*)d_in[22];
    const float* h2_0  = (const float*)d_in[23];
    const float* c2_0  = (const float*)d_in[24];
    float* out = (float*)d_out;

    init_kernel<<<(BB * HSS + 255) / 256, 256>>>(h1_0, c1_0, h2_0, c2_0);
    precompute_kernel<<<dim3(16, 2, 64), 256>>>(listener, Wh, bh, Wv, bv);
    // ctx0 = attend(h2_0); no outputs written
    attend_kernel<<<64, 256>>>(0, 0, Ws, bs, Wout, bout, outputs_length, out, -1);

    for (int t = 0; t < TT; ++t) {
        int p = t & 1;
        lstm_kernel<1><<<128, 128>>>(embed, targets, Wih1, bih1, Whh1, bhh1, p, t);
        lstm_kernel<2><<<128, 128>>>(embed, targets, Wih2, bih2, Whh2, bhh2, p, t);
        attend_kernel<<<64, 256>>>(1 - p, 1 - p, Ws, bs, Wout, bout, outputs_length, out, t);
    }
}

// round 6
// speedup vs baseline: 1.6157x; 1.6157x over previous
#include <cuda_runtime.h>
#include <math.h>

#define BB 64
#define LL 512
#define HLL 512
#define HSS 512
#define EE 256
#define KK 128
#define VV 128
#define CC 34
#define TT 200
#define TP1 201

#define NBLK 128
#define NTHR 256

// smem strides (floats). Chosen %4==0 (float4) and ≡4 mod 8 (bank spread).
#define W1S 228   // 224 used
#define W2S 260   // 256 used
#define A1S 228
#define A2S 260

// smem layout (float offsets)
#define OFF_W1 0
#define OFF_W2 14592            // 64*228
#define OFF_A  31232            // + 64*260
#define OFF_TGT 47872           // + 64*260
#define SMEM_FLOATS 47936
#define SMEM_BYTES (SMEM_FLOATS * 4)

// ---------------- device scratch ----------------
__device__ __align__(16) float g_keypT[BB * KK * LL];   // [b][k][l]
__device__ __align__(16) float g_valp [BB * LL * VV];   // [b][l][v]
__device__ __align__(16) float g_h1[BB * HSS];
__device__ __align__(16) float g_c1[BB * HSS];
__device__ __align__(16) float g_h2[BB * HSS];
__device__ __align__(16) float g_c2[BB * HSS];
__device__ __align__(16) float g_ctx[BB * VV];
__device__ __align__(16) float g_part1[4 * 2048 * 64];  // [ks][j][b]
__device__ __align__(16) float g_part2[4 * 64 * 2048];  // [ks][b][j]
__device__ unsigned g_bar_cnt;
__device__ unsigned g_bar_gen;

// ---------------- init ----------------
__global__ void init_kernel(const float* __restrict__ h1_0, const float* __restrict__ c1_0,
                            const float* __restrict__ h2_0, const float* __restrict__ c2_0) {
    int i = blockIdx.x * blockDim.x + threadIdx.x;
    if (i < BB * HSS) {
        g_h1[i] = h1_0[i];
        g_c1[i] = c1_0[i];
        g_h2[i] = h2_0[i];
        g_c2[i] = c2_0[i];
    }
    if (i == 0) { g_bar_cnt = 0; g_bar_gen = 0; }
}

// ---------------- precompute keypT / valp (unchanged, proven) --------------
__global__ __launch_bounds__(256) void precompute_kernel(
    const float* __restrict__ listener,
    const float* __restrict__ Wh, const float* __restrict__ bh,
    const float* __restrict__ Wv, const float* __restrict__ bv) {
    __shared__ __align__(16) float A_s[32][36];
    __shared__ __align__(16) float W_s[32][132];

    const int b   = blockIdx.z;
    const int ng  = blockIdx.y;
    const int l0t = blockIdx.x * 32;
    const int tid = threadIdx.x;
    const float* W    = ng ? Wv : Wh;
    const float* bias = ng ? bv : bh;

    const int n0 = (tid & 31) * 4;
    const int l0 = (tid >> 5) * 4;
    float acc[4][4] = {};

    for (int kc = 0; kc < HLL; kc += 32) {
        #pragma unroll
        for (int it = 0; it < 4; ++it) {
            int idx = tid + it * 256;
            int k = idx & 31, l = idx >> 5;
            A_s[k][l] = listener[((size_t)b * LL + l0t + l) * HLL + kc + k];
        }
        #pragma unroll
        for (int it = 0; it < 16; ++it) {
            int idx = tid + it * 256;
            int k = idx & 31, n = idx >> 5;
            W_s[k][n] = W[(size_t)n * HLL + kc + k];
        }
        __syncthreads();
        #pragma unroll
        for (int k = 0; k < 32; ++k) {
            float4 a4 = *reinterpret_cast<const float4*>(&A_s[k][l0]);
            float4 w4 = *reinterpret_cast<const float4*>(&W_s[k][n0]);
            float al[4] = {a4.x, a4.y, a4.z, a4.w};
            float wn[4] = {w4.x, w4.y, w4.z, w4.w};
            #pragma unroll
            for (int i = 0; i < 4; ++i)
                #pragma unroll
                for (int j = 0; j < 4; ++j)
                    acc[i][j] += al[i] * wn[j];
        }
        __syncthreads();
    }

    float bn[4] = {bias[n0], bias[n0 + 1], bias[n0 + 2], bias[n0 + 3]};
    if (ng == 0) {
        #pragma unroll
        for (int j = 0; j < 4; ++j)
            #pragma unroll
            for (int i = 0; i < 4; ++i)
                g_keypT[(size_t)b * KK * LL + (size_t)(n0 + j) * LL + (l0t + l0 + i)] =
                    acc[i][j] + bn[j];
    } else {
        #pragma unroll
        for (int i = 0; i < 4; ++i)
            #pragma unroll
            for (int j = 0; j < 4; ++j)
                g_valp[(size_t)b * LL * VV + (size_t)(l0t + l0 + i) * VV + (n0 + j)] =
                    acc[i][j] + bn[j];
    }
}

// ---------------- grid barrier ----------------
__device__ __forceinline__ void gridbar() {
    __threadfence();           // drain this thread's global writes (gpu scope)
    __syncthreads();
    if (threadIdx.x == 0) {
        unsigned gen = *(volatile unsigned*)&g_bar_gen;
        if (atomicAdd(&g_bar_cnt, 1u) == NBLK - 1) {
            g_bar_cnt = 0;
            __threadfence();
            *(volatile unsigned*)&g_bar_gen = gen + 1;
        } else {
            while (*(volatile unsigned*)&g_bar_gen == gen) __nanosleep(32);
        }
        __threadfence();       // acquire: invalidate L1 before post-barrier reads
    }
    __syncthreads();
}

__device__ __forceinline__ float sigf(float x) { return 1.f / (1.f + expf(-x)); }

// ---------------- cell2 + attend + logits (one block == one batch) ---------
__device__ void cell2_attend(float* sm, int b, int t, bool do_cell,
                             const float* __restrict__ bih2, const float* __restrict__ bhh2,
                             const float* __restrict__ Ws, const float* __restrict__ bs,
                             const float* __restrict__ Wout, const float* __restrict__ bout,
                             const int* __restrict__ outputs_length,
                             float* __restrict__ out) {
    float* h2s  = sm + OFF_A;
    float* q    = h2s + 512;
    float* attn = q + 128;
    float* red  = attn + 512;
    float* ctxs = red + 256;
    const int tid = threadIdx.x;

    if (do_cell) {
        #pragma unroll
        for (int uu = 0; uu < 2; ++uu) {
            int u = tid + uu * 256;
            float g[4];
            #pragma unroll
            for (int gate = 0; gate < 4; ++gate) {
                int r = gate * 512 + u;
                float s = bih2[r] + bhh2[r];
                #pragma unroll
                for (int ks2 = 0; ks2 < 4; ++ks2)
                    s += g_part2[((size_t)ks2 * 64 + b) * 2048 + r];
                g[gate] = s;
            }
            float cp = g_c2[b * 512 + u];
            float cn = sigf(g[1]) * cp + sigf(g[0]) * tanhf(g[2]);
            float hn = sigf(g[3]) * tanhf(cn);
            g_c2[b * 512 + u] = cn;
            g_h2[b * 512 + u] = hn;
            h2s[u] = hn;
        }
    } else {
        h2s[tid]       = g_h2[b * 512 + tid];
        h2s[tid + 256] = g_h2[b * 512 + tid + 256];
    }
    __syncthreads();

    // q = h2 @ Ws^T + bs
    if (tid < 128) {
        const float* wr = Ws + (size_t)tid * 512;
        float s = 0.f;
        #pragma unroll 8
        for (int j = 0; j < 512; ++j) s += wr[j] * h2s[j];
        q[tid] = s + bs[tid];
    }
    __syncthreads();

    const int len = (b == 0) ? LL : outputs_length[b];
    const int l1 = tid, l2 = tid + 256;
    float e1 = 0.f, e2 = 0.f;
    const float* kp = g_keypT + (size_t)b * KK * LL;
    #pragma unroll 4
    for (int k = 0; k < 128; ++k) {
        float qk = q[k];
        e1 += qk * kp[k * 512 + l1];
        e2 += qk * kp[k * 512 + l2];
    }
    red[tid] = fmaxf((l1 < len) ? e1 : -1e30f, (l2 < len) ? e2 : -1e30f);
    __syncthreads();
    for (int s = 128; s >= 1; s >>= 1) {
        if (tid < s) red[tid] = fmaxf(red[tid], red[tid + s]);
        __syncthreads();
    }
    float mx = red[0];
    __syncthreads();
    float p1 = (l1 < len) ? expf(e1 - mx) : 0.f;
    float p2 = (l2 < len) ? expf(e2 - mx) : 0.f;
    red[tid] = p1 + p2;
    __syncthreads();
    for (int s = 128; s >= 1; s >>= 1) {
        if (tid < s) red[tid] += red[tid + s];
        __syncthreads();
    }
    float inv = 1.f / fmaxf(red[0], 1e-12f);
    float a1 = p1 * inv, a2 = p2 * inv;
    attn[l1] = a1;
    attn[l2] = a2;
    if (t >= 0) {
        float* ao = out + (size_t)BB * TT * CC + ((size_t)b * TT + t) * LL;
        ao[l1] = a1;
        ao[l2] = a2;
    }
    __syncthreads();

    // ctx = attn @ valp
    {
        int v = tid & 127, half = tid >> 7;
        const float* vp = g_valp + (size_t)b * LL * VV;
        float s = 0.f;
        int lbeg = half * 256;
        #pragma unroll 4
        for (int l = lbeg; l < lbeg + 256; ++l) s += attn[l] * vp[l * VV + v];
        red[tid] = s;
    }
    __syncthreads();
    if (tid < 128) {
        float c = red[tid] + red[tid + 128];
        ctxs[tid] = c;
        g_ctx[b * 128 + tid] = c;
    }
    __syncthreads();

    if (t >= 0) {
        int lane = tid & 31, wrp = tid >> 5;
        for (int c = wrp; c < CC; c += 8) {
            const float* wr = Wout + (size_t)c * 640;
            float s = 0.f;
            #pragma unroll
            for (int j = lane; j < 512; j += 32) s += wr[j] * h2s[j];
            #pragma unroll
            for (int j = lane; j < 128; j += 32) s += wr[512 + j] * ctxs[j];
            #pragma unroll
            for (int o = 16; o > 0; o >>= 1) s += __shfl_xor_sync(0xffffffffu, s, o);
            if (lane == 0) out[((size_t)b * TT + t) * CC + c] = s + bout[c];
        }
    }
}

// ---------------- persistent decoder ----------------
__global__ __launch_bounds__(NTHR, 1) void speller_persistent(
    const int* __restrict__ targets,
    const float* __restrict__ embed,
    const float* __restrict__ Wih1, const float* __restrict__ bih1,
    const float* __restrict__ Whh1, const float* __restrict__ bhh1,
    const float* __restrict__ Wih2, const float* __restrict__ bih2,
    const float* __restrict__ Whh2, const float* __restrict__ bhh2,
    const float* __restrict__ Ws, const float* __restrict__ bs,
    const float* __restrict__ Wout, const float* __restrict__ bout,
    const int* __restrict__ outputs_length,
    float* __restrict__ out) {
    extern __shared__ __align__(16) float sm[];
    float* W1s  = sm + OFF_W1;     // [64][W1S]
    float* W2s  = sm + OFF_W2;     // [64][W2S]
    float* As   = sm + OFF_A;      // [64][A2S] max
    int*   tgts = (int*)(sm + OFF_TGT);

    const int tid = threadIdx.x;
    const int bid = blockIdx.x;
    const int jt  = bid >> 2;          // 0..31
    const int ks  = bid & 3;           // 0..3
    const int tj  = tid >> 4;          // 0..15
    const int tb  = tid & 15;          // 0..15
    const int jl0 = tj * 4, b0 = tb * 4;

    // ---- load this block's weight slices into smem (once) ----
    for (int idx = tid; idx < 64 * 56; idx += NTHR) {
        int jl = idx / 56, kq = idx % 56;
        int j = jt * 64 + jl;
        int k = ks * 224 + kq * 4;
        float4 v = (k < 384)
            ? *reinterpret_cast<const float4*>(&Wih1[(size_t)j * 384 + k])
            : *reinterpret_cast<const float4*>(&Whh1[(size_t)j * 512 + (k - 384)]);
        *reinterpret_cast<float4*>(&W1s[jl * W1S + kq * 4]) = v;
    }
    for (int idx = tid; idx < 64 * 64; idx += NTHR) {
        int jl = idx >> 6, kq = idx & 63;
        int j = jt * 64 + jl;
        int k = ks * 256 + kq * 4;
        float4 v = (k < 512)
            ? *reinterpret_cast<const float4*>(&Wih2[(size_t)j * 512 + k])
            : *reinterpret_cast<const float4*>(&Whh2[(size_t)j * 512 + (k - 512)]);
        *reinterpret_cast<float4*>(&W2s[jl * W2S + kq * 4]) = v;
    }
    __syncthreads();

    // ---- ctx0 = attend(h2_0) ----
    if (bid < 64)
        cell2_attend(sm, bid, -1, false, bih2, bhh2, Ws, bs, Wout, bout, outputs_length, out);
    gridbar();

    const float* w0 = &W1s[(jl0 + 0) * W1S];
    const float* w1 = &W1s[(jl0 + 1) * W1S];
    const float* w2 = &W1s[(jl0 + 2) * W1S];
    const float* w3 = &W1s[(jl0 + 3) * W1S];
    const float* v0 = &W2s[(jl0 + 0) * W2S];
    const float* v1 = &W2s[(jl0 + 1) * W2S];
    const float* v2 = &W2s[(jl0 + 2) * W2S];
    const float* v3 = &W2s[(jl0 + 3) * W2S];

    for (int t = 0; t < TT; ++t) {
        // ===== phase 1: gates1 partial GEMM =====
        if (tid < 64) tgts[tid] = targets[tid * TP1 + t];
        __syncthreads();
        for (int idx = tid; idx < 64 * 56; idx += NTHR) {
            int b = idx / 56, kq = idx % 56;
            int k = ks * 224 + kq * 4;
            float4 v;
            if (k < 256)      v = *reinterpret_cast<const float4*>(&embed[(size_t)tgts[b] * EE + k]);
            else if (k < 384) v = *reinterpret_cast<const float4*>(&g_ctx[b * 128 + (k - 256)]);
            else              v = *reinterpret_cast<const float4*>(&g_h1[b * 512 + (k - 384)]);
            *reinterpret_cast<float4*>(&As[b * A1S + kq * 4]) = v;
        }
        __syncthreads();
        {
            float acc[4][4] = {};
            const float* a0 = &As[(b0 + 0) * A1S];
            const float* a1 = &As[(b0 + 1) * A1S];
            const float* a2 = &As[(b0 + 2) * A1S];
            const float* a3 = &As[(b0 + 3) * A1S];
            #pragma unroll 2
            for (int kq = 0; kq < 56; ++kq) {
                float4 W[4], A[4];
                W[0] = *reinterpret_cast<const float4*>(w0 + kq * 4);
                W[1] = *reinterpret_cast<const float4*>(w1 + kq * 4);
                W[2] = *reinterpret_cast<const float4*>(w2 + kq * 4);
                W[3] = *reinterpret_cast<const float4*>(w3 + kq * 4);
                A[0] = *reinterpret_cast<const float4*>(a0 + kq * 4);
                A[1] = *reinterpret_cast<const float4*>(a1 + kq * 4);
                A[2] = *reinterpret_cast<const float4*>(a2 + kq * 4);
                A[3] = *reinterpret_cast<const float4*>(a3 + kq * 4);
                #pragma unroll
                for (int i = 0; i < 4; ++i)
                    #pragma unroll
                    for (int j = 0; j < 4; ++j)
                        acc[i][j] += W[i].x * A[j].x + W[i].y * A[j].y +
                                     W[i].z * A[j].z + W[i].w * A[j].w;
            }
            #pragma unroll
            for (int i = 0; i < 4; ++i)
                *reinterpret_cast<float4*>(
                    &g_part1[((size_t)ks * 2048 + jt * 64 + jl0 + i) * 64 + b0]) =
                    make_float4(acc[i][0], acc[i][1], acc[i][2], acc[i][3]);
        }
        gridbar();

        // ===== phase 2: cell1 =====
        {
            int b = tid & 63, ul = tid >> 6;
            int u = bid * 4 + ul;
            float g[4];
            #pragma unroll
            for (int gate = 0; gate < 4; ++gate) {
                int r = gate * 512 + u;
                float s = bih1[r] + bhh1[r];
                #pragma unroll
                for (int ks2 = 0; ks2 < 4; ++ks2)
                    s += g_part1[((size_t)ks2 * 2048 + r) * 64 + b];
                g[gate] = s;
            }
            float cp = g_c1[b * 512 + u];
            float cn = sigf(g[1]) * cp + sigf(g[0]) * tanhf(g[2]);
            float hn = sigf(g[3]) * tanhf(cn);
            g_c1[b * 512 + u] = cn;
            g_h1[b * 512 + u] = hn;
        }
        gridbar();

        // ===== phase 3: gates2 partial GEMM =====
        for (int idx = tid; idx < 64 * 64; idx += NTHR) {
            int b = idx >> 6, kq = idx & 63;
            int k = ks * 256 + kq * 4;
            float4 v = (k < 512)
                ? *reinterpret_cast<const float4*>(&g_h1[b * 512 + k])
                : *reinterpret_cast<const float4*>(&g_h2[b * 512 + (k - 512)]);
            *reinterpret_cast<float4*>(&As[b * A2S + kq * 4]) = v;
        }
        __syncthreads();
        {
            float acc[4][4] = {};
            const float* a0 = &As[(b0 + 0) * A2S];
            const float* a1 = &As[(b0 + 1) * A2S];
            const float* a2 = &As[(b0 + 2) * A2S];
            const float* a3 = &As[(b0 + 3) * A2S];
            #pragma unroll 2
            for (int kq = 0; kq < 64; ++kq) {
                float4 W[4], A[4];
                W[0] = *reinterpret_cast<const float4*>(v0 + kq * 4);
                W[1] = *reinterpret_cast<const float4*>(v1 + kq * 4);
                W[2] = *reinterpret_cast<const float4*>(v2 + kq * 4);
                W[3] = *reinterpret_cast<const float4*>(v3 + kq * 4);
                A[0] = *reinterpret_cast<const float4*>(a0 + kq * 4);
                A[1] = *reinterpret_cast<const float4*>(a1 + kq * 4);
                A[2] = *reinterpret_cast<const float4*>(a2 + kq * 4);
                A[3] = *reinterpret_cast<const float4*>(a3 + kq * 4);
                #pragma unroll
                for (int i = 0; i < 4; ++i)
                    #pragma unroll
                    for (int j = 0; j < 4; ++j)
                        acc[i][j] += W[i].x * A[j].x + W[i].y * A[j].y +
                                     W[i].z * A[j].z + W[i].w * A[j].w;
            }
            #pragma unroll
            for (int jb = 0; jb < 4; ++jb)
                *reinterpret_cast<float4*>(
                    &g_part2[((size_t)ks * 64 + b0 + jb) * 2048 + jt * 64 + jl0]) =
                    make_float4(acc[0][jb], acc[1][jb], acc[2][jb], acc[3][jb]);
        }
        gridbar();

        // ===== phase 4: cell2 + attend + logits =====
        if (bid < 64)
            cell2_attend(sm, bid, t, true, bih2, bhh2, Ws, bs, Wout, bout,
                         outputs_length, out);
        gridbar();
    }
}

// ---------------- launch ----------------
extern "C" void kernel_launch(void* const* d_in, const int* in_sizes, int n_in,
                              void* d_out, int out_size) {
    const float* listener       = (const float*)d_in[0];
    const int*   outputs_length = (const int*)  d_in[1];
    const int*   targets        = (const int*)  d_in[2];
    const float* embed = (const float*)d_in[4];
    const float* Ws    = (const float*)d_in[5];
    const float* bs    = (const float*)d_in[6];
    const float* Wh    = (const float*)d_in[7];
    const float* bh    = (const float*)d_in[8];
    const float* Wv    = (const float*)d_in[9];
    const float* bv    = (const float*)d_in[10];
    const float* Wih1  = (const float*)d_in[11];
    const float* bih1  = (const float*)d_in[12];
    const float* Whh1  = (const float*)d_in[13];
    const float* bhh1  = (const float*)d_in[14];
    const float* Wih2  = (const float*)d_in[15];
    const float* bih2  = (const float*)d_in[16];
    const float* Whh2  = (const float*)d_in[17];
    const float* bhh2  = (const float*)d_in[18];
    const float* Wout  = (const float*)d_in[19];
    const float* bout  = (const float*)d_in[20];
    const float* h1_0  = (const float*)d_in[21];
    const float* c1_0  = (const float*)d_in[22];
    const float* h2_0  = (const float*)d_in[23];
    const float* c2_0  = (const float*)d_in[24];
    float* out = (float*)d_out;

    cudaFuncSetAttribute(speller_persistent,
                         cudaFuncAttributeMaxDynamicSharedMemorySize, SMEM_BYTES);

    init_kernel<<<(BB * HSS + 255) / 256, 256>>>(h1_0, c1_0, h2_0, c2_0);
    precompute_kernel<<<dim3(16, 2, 64), 256>>>(listener, Wh, bh, Wv, bv);
    speller_persistent<<<NBLK, NTHR, SMEM_BYTES>>>(
        targets, embed,
        Wih1, bih1, Whh1, bhh1,
        Wih2, bih2, Whh2, bhh2,
        Ws, bs, Wout, bout,
        outputs_length, out);
}